// round 15
// baseline (speedup 1.0000x reference)
#include <cuda_runtime.h>
#include <math.h>

#define BBx 2
#define LLx 2048
#define HHx 8
#define PPx 64
#define DIx 512
#define NDx 16
#define QQx 300
#define QPx 320
#define LDZ 1040
#define NTOK 4096
#define NQx 600

typedef unsigned long long u64;

__device__ __align__(16) float g_zx  [NTOK*LDZ];
__device__ __align__(16) float g_init[NQx*DIx];
__device__ __align__(16) float g_dA  [NTOK*HHx*QPx];
__device__ __align__(16) float g_dtB [NTOK*HHx*QPx];
__device__ __align__(16) float g_C   [NTOK*QPx];
__device__ __align__(16) float g_y   [NTOK*DIx];
__device__ __align__(16) float g_S   [NQx*DIx];
__device__ __align__(16) float g_kf  [NTOK*DIx];
__device__ __align__(16) float g_ln  [NQx*DIx];

__device__ __forceinline__ void ld4(const float* p, float* v) {
    float4 t = *(const float4*)p;
    v[0]=t.x; v[1]=t.y; v[2]=t.z; v[3]=t.w;
}
__device__ __forceinline__ u64 f2mul(u64 a, u64 b){
    u64 r; asm("mul.rn.f32x2 %0,%1,%2;":"=l"(r):"l"(a),"l"(b)); return r;
}
__device__ __forceinline__ u64 f2fma(u64 a, u64 b, u64 c){
    u64 r; asm("fma.rn.f32x2 %0,%1,%2,%3;":"=l"(r):"l"(a),"l"(b),"l"(c)); return r;
}
__device__ __forceinline__ u64 fdup(float x){
    u64 r; asm("mov.b64 %0,{%1,%1};":"=l"(r):"f"(x)); return r;
}
__device__ __forceinline__ u64 fpack(float lo, float hi){
    u64 r; asm("mov.b64 %0,{%1,%2};":"=l"(r):"f"(lo),"f"(hi)); return r;
}
__device__ __forceinline__ void funpk(u64 v, float& lo, float& hi){
    asm("mov.b64 {%0,%1},%2;":"=f"(lo),"=f"(hi):"l"(v));
}

// ---------- 128x128x8 double-buffered SGEMM: C[M,N] = A[M,K] @ B[N,K]^T ----------
// K % 8 == 0. 256 threads, 8x8 per thread.
__global__ __launch_bounds__(256) void sgemm_nt(
    int M, int N, int K,
    const float* __restrict__ A, const float* __restrict__ B,
    float* __restrict__ C, int ldc)
{
    __shared__ float As[2][8][128];
    __shared__ float Bs[2][8][128];
    const int tid = threadIdx.x;
    const int tx = tid & 15;          // n-dir
    const int ty = tid >> 4;          // m-dir
    const int m0 = blockIdx.y*128, n0 = blockIdx.x*128;
    const int lr = tid >> 1;          // 0..127
    const int lc = (tid & 1) * 4;     // 0 or 4

    float acc[8][8];
#pragma unroll
    for (int i=0;i<8;i++)
#pragma unroll
        for (int j=0;j<8;j++) acc[i][j]=0.f;

#define LOAD_TILE(k0, buf)                                              \
    {                                                                   \
        int gm = m0 + lr;                                               \
        float4 va = make_float4(0.f,0.f,0.f,0.f);                       \
        if (gm < M) va = *(const float4*)(A + (size_t)gm*K + (k0) + lc);\
        As[buf][lc+0][lr]=va.x; As[buf][lc+1][lr]=va.y;                 \
        As[buf][lc+2][lr]=va.z; As[buf][lc+3][lr]=va.w;                 \
        int gn = n0 + lr;                                               \
        float4 vb = make_float4(0.f,0.f,0.f,0.f);                       \
        if (gn < N) vb = *(const float4*)(B + (size_t)gn*K + (k0) + lc);\
        Bs[buf][lc+0][lr]=vb.x; Bs[buf][lc+1][lr]=vb.y;                 \
        Bs[buf][lc+2][lr]=vb.z; Bs[buf][lc+3][lr]=vb.w;                 \
    }

    LOAD_TILE(0, 0);
    __syncthreads();

    int buf = 0;
    for (int k0 = 0; k0 < K; k0 += 8) {
        if (k0 + 8 < K) LOAD_TILE(k0+8, buf^1);
#pragma unroll
        for (int kk=0;kk<8;kk++) {
            float a[8], b[8];
            *(float4*)(a)   = *(const float4*)&As[buf][kk][ty*8];
            *(float4*)(a+4) = *(const float4*)&As[buf][kk][ty*8+4];
            *(float4*)(b)   = *(const float4*)&Bs[buf][kk][tx*8];
            *(float4*)(b+4) = *(const float4*)&Bs[buf][kk][tx*8+4];
#pragma unroll
            for (int i=0;i<8;i++)
#pragma unroll
                for (int j=0;j<8;j++) acc[i][j] = fmaf(a[i], b[j], acc[i][j]);
        }
        __syncthreads();
        buf ^= 1;
    }
#undef LOAD_TILE

#pragma unroll
    for (int i=0;i<8;i++) {
        int gm = m0 + ty*8 + i;
        if (gm < M) {
            float* crow = C + (size_t)gm*ldc;
#pragma unroll
            for (int j4=0;j4<8;j4+=4) {
                int gn = n0 + tx*8 + j4;
                if (gn + 3 < N) {
                    *(float4*)(crow + gn) = make_float4(acc[i][j4],acc[i][j4+1],acc[i][j4+2],acc[i][j4+3]);
                } else {
#pragma unroll
                    for (int j=0;j<4;j++)
                        if (gn + j < N) crow[gn+j] = acc[i][j4+j];
                }
            }
        }
    }
}

// per-token: B,C,dt -> g_dA, g_dtB, g_C (0.5 folded); zeroes g_y/g_S rows.
__global__ __launch_bounds__(QPx) void precompute_kernel(
    const float* __restrict__ dist, const float* __restrict__ W_bc,
    const float* __restrict__ W_dt, const float* __restrict__ dt_bias,
    const float* __restrict__ A_log)
{
    const int bt = blockIdx.x;
    const int n  = threadIdx.x;

    for (int i = n; i < DIx; i += QPx) {
        g_y[(size_t)bt*DIx + i] = 0.f;
        if (bt < NQx) g_S[(size_t)bt*DIx + i] = 0.f;
    }

    __shared__ float swbc[32], swdt[128], sdtb[8], sA[8], stok[10];
    if (n < 32) swbc[n] = W_bc[n];
    if (n >= 32 && n < 160) swdt[n-32] = W_dt[n-32];
    if (n >= 160 && n < 168) {
        sdtb[n-160] = dt_bias[n-160];
        sA[n-160]   = -expf(A_log[n-160]);
    }
    if (n >= 168 && n < 178) stok[n-168] = g_zx[(size_t)bt*LDZ + 1024 + (n-168)];
    __syncthreads();

    const bool valid = (n < QQx);
    float d[16];
    if (valid) {
        const float* dp = dist + ((size_t)bt*QQx + n)*NDx;
        ld4(dp,d); ld4(dp+4,d+4); ld4(dp+8,d+8); ld4(dp+12,d+12);
    } else {
#pragma unroll
        for (int i=0;i<16;i++) d[i]=0.f;
    }
    float bc0=0.f, bc1=0.f;
#pragma unroll
    for (int i=0;i<16;i++) {
        bc0 = fmaf(d[i], swbc[i],    bc0);
        bc1 = fmaf(d[i], swbc[16+i], bc1);
    }
    float Bv = bc0 + stok[0];
    float Cv = bc1 + stok[1];
    g_C[(size_t)bt*QPx + n] = valid ? 0.5f*Cv : 0.f;
#pragma unroll
    for (int h=0;h<8;h++) {
        float db = 0.f;
#pragma unroll
        for (int i=0;i<16;i++) db = fmaf(d[i], swdt[h*16+i], db);
        float v  = db + stok[2+h] + sdtb[h];
        float dt = (v > 20.f) ? v : log1pf(expf(v));
        size_t o = ((size_t)bt*HHx + h)*QPx + n;
        g_dA[o]  = valid ? expf(dt*sA[h]) : 0.f;
        g_dtB[o] = valid ? dt*Bv : 0.f;
    }
}

// scan (R12, proven): compile-time strides, immediate-offset loads; 2p x 4n
// tiles; f32x2 math; 8-step recursive-halving reduction; atomicAdd into g_y.
template<int STP>
__device__ __forceinline__ void scan_body(int pg, int h, int b) {
    const int tid = threadIdx.x, w = tid >> 5, lane = tid & 31;
    const int wn = w >> 1, wp = w & 1;
    const int p_pair = lane >> 3, n_sub = lane & 7;
    const int n0 = wn*32 + n_sub*4;
    const int p0 = pg*16 + wp*8 + p_pair*2;

    constexpr long SA = (long)STP*(HHx*QPx);
    constexpr long SC = (long)STP*QPx;
    constexpr long SX = (long)STP*LDZ;
    constexpr long SY = (long)STP*DIx;

    u64 S0p[2], S1p[2];
#pragma unroll
    for (int jp=0;jp<2;jp++) {
        float s0a=0.f,s0b=0.f,s1a=0.f,s1b=0.f;
        int na = n0 + 2*jp, nb = na + 1;
        if (na < QQx) {
            const float* ip = &g_init[((size_t)(b*QQx+na))*DIx + h*PPx + p0];
            s0a = ip[0]; s1a = ip[1];
        }
        if (nb < QQx) {
            const float* ip = &g_init[((size_t)(b*QQx+nb))*DIx + h*PPx + p0];
            s0b = ip[0]; s1b = ip[1];
        }
        S0p[jp] = fpack(s0a, s0b);
        S1p[jp] = fpack(s1a, s1b);
    }

    const int bL = b*LLx;
    const int t0 = (STP < 0) ? (LLx-1) : 0;

    const float* pA = g_dA  + ((size_t)(bL+t0)*HHx + h)*QPx + n0;
    const float* pU = g_dtB + ((size_t)(bL+t0)*HHx + h)*QPx + n0;
    const float* pC = g_C   + (size_t)(bL+t0)*QPx + n0;
    const float* pX = g_zx  + (size_t)(bL+t0)*LDZ + DIx + h*PPx + p0;
    float*       pY = g_y   + (size_t)(bL+t0)*DIx + h*PPx + p0;
    float*       pYl = pY + (long)n_sub*SY;

    u64 av[4][2], uv[4][2], cv[4][2];
    float xv[4][2];
#pragma unroll
    for (int i=0;i<4;i++) {
        ulonglong2 ta = *(const ulonglong2*)(pA + i*SA); av[i][0]=ta.x; av[i][1]=ta.y;
        ulonglong2 tu = *(const ulonglong2*)(pU + i*SA); uv[i][0]=tu.x; uv[i][1]=tu.y;
        ulonglong2 tc = *(const ulonglong2*)(pC + i*SC); cv[i][0]=tc.x; cv[i][1]=tc.y;
        float2 t = *(const float2*)(pX + i*SX); xv[i][0]=t.x; xv[i][1]=t.y;
    }
    pA += 4*SA; pU += 4*SA; pC += 4*SC; pX += 4*SX;

    float yb0[8], yb1[8];

    for (int s0 = 0; s0 < LLx; s0 += 8) {
        const bool g1ld = (s0 + 8 < LLx);
#pragma unroll
        for (int g = 0; g < 2; g++) {
#pragma unroll
            for (int i=0;i<4;i++) {
                u64 xd0 = fdup(xv[i][0]);
                u64 xd1 = fdup(xv[i][1]);
                u64 y0 = 0ULL, y1 = 0ULL;
#pragma unroll
                for (int jp=0;jp<2;jp++) {
                    S0p[jp] = f2fma(S0p[jp], av[i][jp], f2mul(uv[i][jp], xd0));
                    y0 = f2fma(S0p[jp], cv[i][jp], y0);
                    S1p[jp] = f2fma(S1p[jp], av[i][jp], f2mul(uv[i][jp], xd1));
                    y1 = f2fma(S1p[jp], cv[i][jp], y1);
                }
                if (g == 0 || g1ld) {
                    const long o = (g*4 + i);
                    ulonglong2 ta = *(const ulonglong2*)(pA + o*SA); av[i][0]=ta.x; av[i][1]=ta.y;
                    ulonglong2 tu = *(const ulonglong2*)(pU + o*SA); uv[i][0]=tu.x; uv[i][1]=tu.y;
                    ulonglong2 tc = *(const ulonglong2*)(pC + o*SC); cv[i][0]=tc.x; cv[i][1]=tc.y;
                    float2 t = *(const float2*)(pX + o*SX); xv[i][0]=t.x; xv[i][1]=t.y;
                }
                float a0,b0,a1,b1;
                funpk(y0, a0, b0);
                funpk(y1, a1, b1);
                yb0[g*4+i] = a0 + b0;
                yb1[g*4+i] = a1 + b1;
            }
        }
        pA += 8*SA; pU += 8*SA; pC += 8*SC; pX += 8*SX;

        // recursive-halving over the 8 n_sub lanes; lane n_sub ends with step s0+n_sub
#pragma unroll
        for (int j = 0, m = 1; j < 3; j++, m <<= 1) {
            const int len = 8 >> (j + 1);
            const bool hi = (n_sub & m) != 0;
#pragma unroll
            for (int k = 0; k < len; k++) {
                float send0 = hi ? yb0[2*k]   : yb0[2*k+1];
                float send1 = hi ? yb1[2*k]   : yb1[2*k+1];
                float keep0 = hi ? yb0[2*k+1] : yb0[2*k];
                float keep1 = hi ? yb1[2*k+1] : yb1[2*k];
                float r0 = __shfl_xor_sync(0xffffffffu, send0, m);
                float r1 = __shfl_xor_sync(0xffffffffu, send1, m);
                yb0[k] = keep0 + r0;
                yb1[k] = keep1 + r1;
            }
        }
        atomicAdd(pYl,   yb0[0]);
        atomicAdd(pYl+1, yb1[0]);
        pYl += 8*SY;
    }

#pragma unroll
    for (int jp=0;jp<2;jp++) {
        float s0a,s0b,s1a,s1b;
        funpk(S0p[jp], s0a, s0b);
        funpk(S1p[jp], s1a, s1b);
        int na = n0 + 2*jp, nb = na + 1;
        if (na < QQx) {
            float* sp = &g_S[((size_t)(b*QQx+na))*DIx + h*PPx + p0];
            atomicAdd(sp,   0.5f*s0a);
            atomicAdd(sp+1, 0.5f*s1a);
        }
        if (nb < QQx) {
            float* sp = &g_S[((size_t)(b*QQx+nb))*DIx + h*PPx + p0];
            atomicAdd(sp,   0.5f*s0b);
            atomicAdd(sp+1, 0.5f*s1b);
        }
    }
}

__global__ __launch_bounds__(640, 1) void scan_kernel() {
    const int bx  = blockIdx.x;
    const int pg  = bx & 3;
    const int h   = (bx >> 2) & 7;
    const int b   = (bx >> 5) & 1;
    const int dir = (bx >> 6) & 1;
    if (dir == 0) scan_body<1>(pg, h, b);
    else          scan_body<-1>(pg, h, b);
}

__global__ __launch_bounds__(256) void gate_rms_kernel(
    const float* __restrict__ Dv, const float* __restrict__ knw)
{
    const int row = blockIdx.x, tid = threadIdx.x;
    float g[2]; float ss = 0.f;
#pragma unroll
    for (int e2=0;e2<2;e2++) {
        int e = tid + e2*256;
        float y = g_y [(size_t)row*DIx + e];
        float x = g_zx[(size_t)row*LDZ + DIx + e];
        float z = g_zx[(size_t)row*LDZ + e];
        float gg = (y + x*Dv[e>>6]) * (z / (1.f + expf(-z)));
        g[e2] = gg;
        ss += gg*gg;
    }
#pragma unroll
    for (int o=16;o;o>>=1) ss += __shfl_xor_sync(0xffffffffu, ss, o);
    __shared__ float red[8];
    if ((tid & 31) == 0) red[tid>>5] = ss;
    __syncthreads();
    if (tid == 0) {
        float tot = 0.f;
#pragma unroll
        for (int i=0;i<8;i++) tot += red[i];
        red[0] = rsqrtf(tot/512.f + 1e-5f);
    }
    __syncthreads();
    float sc = red[0];
#pragma unroll
    for (int e2=0;e2<2;e2++) {
        int e = tid + e2*256;
        g_kf[(size_t)row*DIx + e] = g[e2]*sc*knw[e];
    }
}

__global__ __launch_bounds__(256) void lnorm_kernel(
    const float* __restrict__ wn, const float* __restrict__ bn)
{
    const int row = blockIdx.x, tid = threadIdx.x;
    float v[2]; float s1 = 0.f, s2 = 0.f;
#pragma unroll
    for (int e2=0;e2<2;e2++) {
        int e = tid + e2*256;
        float x = g_S[(size_t)row*DIx + e];
        v[e2] = x; s1 += x; s2 += x*x;
    }
#pragma unroll
    for (int o=16;o;o>>=1) {
        s1 += __shfl_xor_sync(0xffffffffu, s1, o);
        s2 += __shfl_xor_sync(0xffffffffu, s2, o);
    }
    __shared__ float r1[8], r2[8];
    if ((tid & 31) == 0) { r1[tid>>5] = s1; r2[tid>>5] = s2; }
    __syncthreads();
    __shared__ float smu, sisd;
    if (tid == 0) {
        float a=0.f, bq=0.f;
#pragma unroll
        for (int i=0;i<8;i++) { a += r1[i]; bq += r2[i]; }
        float mu = a/512.f;
        smu = mu;
        sisd = rsqrtf(bq/512.f - mu*mu + 1e-5f);
    }
    __syncthreads();
    float mu = smu, isd = sisd;
#pragma unroll
    for (int e2=0;e2<2;e2++) {
        int e = tid + e2*256;
        g_ln[(size_t)row*DIx + e] = (v[e2]-mu)*isd*wn[e] + bn[e];
    }
}

extern "C" void kernel_launch(void* const* d_in, const int* in_sizes, int n_in,
                              void* d_out, int out_size) {
    const float* in_key    = (const float*)d_in[0];
    const float* in_query  = (const float*)d_in[1];
    const float* dist      = (const float*)d_in[2];
    const float* W_key     = (const float*)d_in[3];
    const float* W_query   = (const float*)d_in[4];
    const float* W_bc      = (const float*)d_in[5];
    const float* W_dt      = (const float*)d_in[6];
    const float* dt_bias   = (const float*)d_in[7];
    const float* A_log     = (const float*)d_in[8];
    const float* Dv        = (const float*)d_in[9];
    const float* W_out_key = (const float*)d_in[10];
    const float* W_out_qry = (const float*)d_in[11];
    const float* key_nw    = (const float*)d_in[12];
    const float* q_nw      = (const float*)d_in[13];
    const float* q_nb      = (const float*)d_in[14];
    float* out = (float*)d_out;

    float *p_zx, *p_init, *p_kf, *p_ln;
    cudaGetSymbolAddress((void**)&p_zx,   g_zx);
    cudaGetSymbolAddress((void**)&p_init, g_init);
    cudaGetSymbolAddress((void**)&p_kf,   g_kf);
    cudaGetSymbolAddress((void**)&p_ln,   g_ln);

    sgemm_nt<<<dim3(9,32), 256>>>(NTOK, 1034, 256, in_key,   W_key,   p_zx,   LDZ);
    sgemm_nt<<<dim3(4,5),  256>>>(NQx,  512,  256, in_query, W_query, p_init, DIx);
    precompute_kernel<<<NTOK, QPx>>>(dist, W_bc, W_dt, dt_bias, A_log);
    scan_kernel<<<128, 640>>>();
    gate_rms_kernel<<<NTOK, 256>>>(Dv, key_nw);
    lnorm_kernel<<<NQx, 256>>>(q_nw, q_nb);
    sgemm_nt<<<dim3(2,32), 256>>>(NTOK, 256, 512, p_kf, W_out_key, out, 256);
    sgemm_nt<<<dim3(2,5),  256>>>(NQx,  256, 512, p_ln, W_out_qry, out + (size_t)NTOK*256, 256);
}

// round 16
// speedup vs baseline: 1.2325x; 1.2325x over previous
#include <cuda_runtime.h>
#include <math.h>

#define BBx 2
#define LLx 2048
#define HHx 8
#define PPx 64
#define DIx 512
#define NDx 16
#define QQx 300
#define QPx 320
#define LDZ 1040
#define NTOK 4096
#define NQx 600

typedef unsigned long long u64;

__device__ __align__(16) float g_zx  [NTOK*LDZ];
__device__ __align__(16) float g_init[NQx*DIx];
__device__ __align__(16) float g_dA  [NTOK*HHx*QPx];
__device__ __align__(16) float g_dtB [NTOK*HHx*QPx];
__device__ __align__(16) float g_C   [NTOK*QPx];
__device__ __align__(16) float g_y   [NTOK*DIx];
__device__ __align__(16) float g_S   [NQx*DIx];
__device__ __align__(16) float g_kf  [NTOK*DIx];
__device__ __align__(16) float g_ln  [NQx*DIx];

__device__ __forceinline__ void ld4(const float* p, float* v) {
    float4 t = *(const float4*)p;
    v[0]=t.x; v[1]=t.y; v[2]=t.z; v[3]=t.w;
}
__device__ __forceinline__ u64 f2mul(u64 a, u64 b){
    u64 r; asm("mul.rn.f32x2 %0,%1,%2;":"=l"(r):"l"(a),"l"(b)); return r;
}
__device__ __forceinline__ u64 f2fma(u64 a, u64 b, u64 c){
    u64 r; asm("fma.rn.f32x2 %0,%1,%2,%3;":"=l"(r):"l"(a),"l"(b),"l"(c)); return r;
}
__device__ __forceinline__ u64 fdup(float x){
    u64 r; asm("mov.b64 %0,{%1,%1};":"=l"(r):"f"(x)); return r;
}
__device__ __forceinline__ u64 fpack(float lo, float hi){
    u64 r; asm("mov.b64 %0,{%1,%2};":"=l"(r):"f"(lo),"f"(hi)); return r;
}
__device__ __forceinline__ void funpk(u64 v, float& lo, float& hi){
    asm("mov.b64 {%0,%1},%2;":"=f"(lo),"=f"(hi):"l"(v));
}

// ---------- R12-proven SGEMM: C[M,N] = A[M,K] @ B[N,K]^T ; K % 16 == 0 ----------
__global__ __launch_bounds__(256) void sgemm_nt(
    int M, int N, int K,
    const float* __restrict__ A, const float* __restrict__ B,
    float* __restrict__ C, int ldc)
{
    __shared__ float As[16][132];
    __shared__ float Bs[16][68];
    const int tid = threadIdx.x;
    const int tx = tid & 15, ty = tid >> 4;
    const int m0 = blockIdx.y*128, n0 = blockIdx.x*64;
    float acc[8][4];
#pragma unroll
    for (int i=0;i<8;i++)
#pragma unroll
        for (int j=0;j<4;j++) acc[i][j]=0.f;

    for (int k0=0;k0<K;k0+=16) {
#pragma unroll
        for (int i=0;i<2;i++) {
            int idx = tid + i*256;
            int ar = idx >> 2, ac = (idx & 3) << 2;
            int gm = m0 + ar;
            float4 v = make_float4(0.f,0.f,0.f,0.f);
            if (gm < M) v = *(const float4*)(A + (size_t)gm*K + k0 + ac);
            As[ac+0][ar]=v.x; As[ac+1][ar]=v.y; As[ac+2][ar]=v.z; As[ac+3][ar]=v.w;
        }
        {
            int br = tid >> 2, bc = (tid & 3) << 2;
            int gn = n0 + br;
            float4 v = make_float4(0.f,0.f,0.f,0.f);
            if (gn < N) v = *(const float4*)(B + (size_t)gn*K + k0 + bc);
            Bs[bc+0][br]=v.x; Bs[bc+1][br]=v.y; Bs[bc+2][br]=v.z; Bs[bc+3][br]=v.w;
        }
        __syncthreads();
#pragma unroll
        for (int kk=0;kk<16;kk++) {
            float a[8], bb[4];
#pragma unroll
            for (int i=0;i<8;i++) a[i] = As[kk][ty*8+i];
            float4 bv = *(const float4*)&Bs[kk][tx*4];
            bb[0]=bv.x; bb[1]=bv.y; bb[2]=bv.z; bb[3]=bv.w;
#pragma unroll
            for (int i=0;i<8;i++)
#pragma unroll
                for (int j=0;j<4;j++) acc[i][j] = fmaf(a[i], bb[j], acc[i][j]);
        }
        __syncthreads();
    }
#pragma unroll
    for (int i=0;i<8;i++) {
        int gm = m0 + ty*8 + i;
        if (gm < M)
#pragma unroll
            for (int j=0;j<4;j++) {
                int gn = n0 + tx*4 + j;
                if (gn < N) C[(size_t)gm*ldc + gn] = acc[i][j];
            }
    }
}

// per-token: B,C,dt -> g_dA, g_dtB, g_C (0.5 folded); zeroes g_y/g_S rows.
__global__ __launch_bounds__(QPx) void precompute_kernel(
    const float* __restrict__ dist, const float* __restrict__ W_bc,
    const float* __restrict__ W_dt, const float* __restrict__ dt_bias,
    const float* __restrict__ A_log)
{
    const int bt = blockIdx.x;
    const int n  = threadIdx.x;

    for (int i = n; i < DIx; i += QPx) {
        g_y[(size_t)bt*DIx + i] = 0.f;
        if (bt < NQx) g_S[(size_t)bt*DIx + i] = 0.f;
    }

    __shared__ float swbc[32], swdt[128], sdtb[8], sA[8], stok[10];
    if (n < 32) swbc[n] = W_bc[n];
    if (n >= 32 && n < 160) swdt[n-32] = W_dt[n-32];
    if (n >= 160 && n < 168) {
        sdtb[n-160] = dt_bias[n-160];
        sA[n-160]   = -expf(A_log[n-160]);
    }
    if (n >= 168 && n < 178) stok[n-168] = g_zx[(size_t)bt*LDZ + 1024 + (n-168)];
    __syncthreads();

    const bool valid = (n < QQx);
    float d[16];
    if (valid) {
        const float* dp = dist + ((size_t)bt*QQx + n)*NDx;
        ld4(dp,d); ld4(dp+4,d+4); ld4(dp+8,d+8); ld4(dp+12,d+12);
    } else {
#pragma unroll
        for (int i=0;i<16;i++) d[i]=0.f;
    }
    float bc0=0.f, bc1=0.f;
#pragma unroll
    for (int i=0;i<16;i++) {
        bc0 = fmaf(d[i], swbc[i],    bc0);
        bc1 = fmaf(d[i], swbc[16+i], bc1);
    }
    float Bv = bc0 + stok[0];
    float Cv = bc1 + stok[1];
    g_C[(size_t)bt*QPx + n] = valid ? 0.5f*Cv : 0.f;
#pragma unroll
    for (int h=0;h<8;h++) {
        float db = 0.f;
#pragma unroll
        for (int i=0;i<16;i++) db = fmaf(d[i], swdt[h*16+i], db);
        float v  = db + stok[2+h] + sdtb[h];
        float dt = (v > 20.f) ? v : log1pf(expf(v));
        size_t o = ((size_t)bt*HHx + h)*QPx + n;
        g_dA[o]  = valid ? expf(dt*sA[h]) : 0.f;
        g_dtB[o] = valid ? dt*Bv : 0.f;
    }
}

// scan v9: 128 blocks (pg4,h8,b2,dir2); 320 threads (10 warps); 4p x 4n thread
// tiles (no wp duplication -> LDG/SM/step halved); 4-deep pipeline; f32x2;
// 8-step recursive-halving reduction; atomicAdd into g_y.
template<int STP>
__device__ __forceinline__ void scan_body(int pg, int h, int b) {
    const int tid = threadIdx.x, w = tid >> 5, lane = tid & 31;
    const int p_pair = lane >> 3, n_sub = lane & 7;
    const int n0 = w*32 + n_sub*4;
    const int p0 = pg*16 + p_pair*4;

    constexpr long SA = (long)STP*(HHx*QPx);
    constexpr long SC = (long)STP*QPx;
    constexpr long SX = (long)STP*LDZ;
    constexpr long SY = (long)STP*DIx;

    // S[pi][jp] = {S(p0+pi, n0+2jp), S(p0+pi, n0+2jp+1)}
    u64 S[4][2];
    {
        float si[4][4];
#pragma unroll
        for (int jn=0;jn<4;jn++) {
            int n = n0 + jn;
            if (n < QQx) ld4(&g_init[((size_t)(b*QQx+n))*DIx + h*PPx + p0], si[jn]);
            else { si[jn][0]=0.f; si[jn][1]=0.f; si[jn][2]=0.f; si[jn][3]=0.f; }
        }
#pragma unroll
        for (int pi=0;pi<4;pi++)
#pragma unroll
            for (int jp=0;jp<2;jp++)
                S[pi][jp] = fpack(si[2*jp][pi], si[2*jp+1][pi]);
    }

    const int bL = b*LLx;
    const int t0 = (STP < 0) ? (LLx-1) : 0;

    const float* pA = g_dA  + ((size_t)(bL+t0)*HHx + h)*QPx + n0;
    const float* pU = g_dtB + ((size_t)(bL+t0)*HHx + h)*QPx + n0;
    const float* pC = g_C   + (size_t)(bL+t0)*QPx + n0;
    const float* pX = g_zx  + (size_t)(bL+t0)*LDZ + DIx + h*PPx + p0;
    float*       pYl = g_y  + (size_t)(bL+t0)*DIx + h*PPx + p0 + (long)n_sub*SY;

    u64 av[4][2], uv[4][2], cv[4][2];
    float xv[4][4];
#pragma unroll
    for (int i=0;i<4;i++) {
        ulonglong2 ta = *(const ulonglong2*)(pA + i*SA); av[i][0]=ta.x; av[i][1]=ta.y;
        ulonglong2 tu = *(const ulonglong2*)(pU + i*SA); uv[i][0]=tu.x; uv[i][1]=tu.y;
        ulonglong2 tc = *(const ulonglong2*)(pC + i*SC); cv[i][0]=tc.x; cv[i][1]=tc.y;
        ld4(pX + i*SX, xv[i]);
    }
    pA += 4*SA; pU += 4*SA; pC += 4*SC; pX += 4*SX;

    float yb[4][8];   // [pi][step-in-group]

    for (int s0 = 0; s0 < LLx; s0 += 8) {
        const bool g1ld = (s0 + 8 < LLx);
#pragma unroll
        for (int g = 0; g < 2; g++) {
#pragma unroll
            for (int i=0;i<4;i++) {
#pragma unroll
                for (int pi=0;pi<4;pi++) {
                    u64 xd = fdup(xv[i][pi]);
                    u64 y  = 0ULL;
#pragma unroll
                    for (int jp=0;jp<2;jp++) {
                        S[pi][jp] = f2fma(S[pi][jp], av[i][jp], f2mul(uv[i][jp], xd));
                        y = f2fma(S[pi][jp], cv[i][jp], y);
                    }
                    float ya, ybv;
                    funpk(y, ya, ybv);
                    yb[pi][g*4+i] = ya + ybv;
                }
                if (g == 0 || g1ld) {
                    const long o = (g*4 + i);
                    ulonglong2 ta = *(const ulonglong2*)(pA + o*SA); av[i][0]=ta.x; av[i][1]=ta.y;
                    ulonglong2 tu = *(const ulonglong2*)(pU + o*SA); uv[i][0]=tu.x; uv[i][1]=tu.y;
                    ulonglong2 tc = *(const ulonglong2*)(pC + o*SC); cv[i][0]=tc.x; cv[i][1]=tc.y;
                    ld4(pX + o*SX, xv[i]);
                }
            }
        }
        pA += 8*SA; pU += 8*SA; pC += 8*SC; pX += 8*SX;

        // recursive halving over 8 n_sub lanes per pi; lane n_sub ends with
        // the full (warp-local) sum of step s0+n_sub.
#pragma unroll
        for (int pi=0;pi<4;pi++) {
#pragma unroll
            for (int j = 0, m = 1; j < 3; j++, m <<= 1) {
                const int len = 8 >> (j + 1);
                const bool hi = (n_sub & m) != 0;
#pragma unroll
                for (int k = 0; k < len; k++) {
                    float send = hi ? yb[pi][2*k]   : yb[pi][2*k+1];
                    float keep = hi ? yb[pi][2*k+1] : yb[pi][2*k];
                    float r = __shfl_xor_sync(0xffffffffu, send, m);
                    yb[pi][k] = keep + r;
                }
            }
        }
        atomicAdd(pYl+0, yb[0][0]);
        atomicAdd(pYl+1, yb[1][0]);
        atomicAdd(pYl+2, yb[2][0]);
        atomicAdd(pYl+3, yb[3][0]);
        pYl += 8*SY;
    }

    // final states -> g_S (0.5 biscan average), 4 consecutive p per n
#pragma unroll
    for (int jp=0;jp<2;jp++) {
        float sa[4], sb[4];
#pragma unroll
        for (int pi=0;pi<4;pi++) funpk(S[pi][jp], sa[pi], sb[pi]);
        int na = n0 + 2*jp, nb = na + 1;
        if (na < QQx) {
            float* sp = &g_S[((size_t)(b*QQx+na))*DIx + h*PPx + p0];
#pragma unroll
            for (int pi=0;pi<4;pi++) atomicAdd(sp+pi, 0.5f*sa[pi]);
        }
        if (nb < QQx) {
            float* sp = &g_S[((size_t)(b*QQx+nb))*DIx + h*PPx + p0];
#pragma unroll
            for (int pi=0;pi<4;pi++) atomicAdd(sp+pi, 0.5f*sb[pi]);
        }
    }
}

__global__ __launch_bounds__(320, 1) void scan_kernel() {
    const int bx  = blockIdx.x;
    const int pg  = bx & 3;
    const int h   = (bx >> 2) & 7;
    const int b   = (bx >> 5) & 1;
    const int dir = (bx >> 6) & 1;
    if (dir == 0) scan_body<1>(pg, h, b);
    else          scan_body<-1>(pg, h, b);
}

__global__ __launch_bounds__(256) void gate_rms_kernel(
    const float* __restrict__ Dv, const float* __restrict__ knw)
{
    const int row = blockIdx.x, tid = threadIdx.x;
    float g[2]; float ss = 0.f;
#pragma unroll
    for (int e2=0;e2<2;e2++) {
        int e = tid + e2*256;
        float y = g_y [(size_t)row*DIx + e];
        float x = g_zx[(size_t)row*LDZ + DIx + e];
        float z = g_zx[(size_t)row*LDZ + e];
        float gg = (y + x*Dv[e>>6]) * (z / (1.f + expf(-z)));
        g[e2] = gg;
        ss += gg*gg;
    }
#pragma unroll
    for (int o=16;o;o>>=1) ss += __shfl_xor_sync(0xffffffffu, ss, o);
    __shared__ float red[8];
    if ((tid & 31) == 0) red[tid>>5] = ss;
    __syncthreads();
    if (tid == 0) {
        float tot = 0.f;
#pragma unroll
        for (int i=0;i<8;i++) tot += red[i];
        red[0] = rsqrtf(tot/512.f + 1e-5f);
    }
    __syncthreads();
    float sc = red[0];
#pragma unroll
    for (int e2=0;e2<2;e2++) {
        int e = tid + e2*256;
        g_kf[(size_t)row*DIx + e] = g[e2]*sc*knw[e];
    }
}

__global__ __launch_bounds__(256) void lnorm_kernel(
    const float* __restrict__ wn, const float* __restrict__ bn)
{
    const int row = blockIdx.x, tid = threadIdx.x;
    float v[2]; float s1 = 0.f, s2 = 0.f;
#pragma unroll
    for (int e2=0;e2<2;e2++) {
        int e = tid + e2*256;
        float x = g_S[(size_t)row*DIx + e];
        v[e2] = x; s1 += x; s2 += x*x;
    }
#pragma unroll
    for (int o=16;o;o>>=1) {
        s1 += __shfl_xor_sync(0xffffffffu, s1, o);
        s2 += __shfl_xor_sync(0xffffffffu, s2, o);
    }
    __shared__ float r1[8], r2[8];
    if ((tid & 31) == 0) { r1[tid>>5] = s1; r2[tid>>5] = s2; }
    __syncthreads();
    __shared__ float smu, sisd;
    if (tid == 0) {
        float a=0.f, bq=0.f;
#pragma unroll
        for (int i=0;i<8;i++) { a += r1[i]; bq += r2[i]; }
        float mu = a/512.f;
        smu = mu;
        sisd = rsqrtf(bq/512.f - mu*mu + 1e-5f);
    }
    __syncthreads();
    float mu = smu, isd = sisd;
#pragma unroll
    for (int e2=0;e2<2;e2++) {
        int e = tid + e2*256;
        g_ln[(size_t)row*DIx + e] = (v[e2]-mu)*isd*wn[e] + bn[e];
    }
}

extern "C" void kernel_launch(void* const* d_in, const int* in_sizes, int n_in,
                              void* d_out, int out_size) {
    const float* in_key    = (const float*)d_in[0];
    const float* in_query  = (const float*)d_in[1];
    const float* dist      = (const float*)d_in[2];
    const float* W_key     = (const float*)d_in[3];
    const float* W_query   = (const float*)d_in[4];
    const float* W_bc      = (const float*)d_in[5];
    const float* W_dt      = (const float*)d_in[6];
    const float* dt_bias   = (const float*)d_in[7];
    const float* A_log     = (const float*)d_in[8];
    const float* Dv        = (const float*)d_in[9];
    const float* W_out_key = (const float*)d_in[10];
    const float* W_out_qry = (const float*)d_in[11];
    const float* key_nw    = (const float*)d_in[12];
    const float* q_nw      = (const float*)d_in[13];
    const float* q_nb      = (const float*)d_in[14];
    float* out = (float*)d_out;

    float *p_zx, *p_init, *p_kf, *p_ln;
    cudaGetSymbolAddress((void**)&p_zx,   g_zx);
    cudaGetSymbolAddress((void**)&p_init, g_init);
    cudaGetSymbolAddress((void**)&p_kf,   g_kf);
    cudaGetSymbolAddress((void**)&p_ln,   g_ln);

    sgemm_nt<<<dim3(17,32), 256>>>(NTOK, 1034, 256, in_key,   W_key,   p_zx,   LDZ);
    sgemm_nt<<<dim3(8,5),   256>>>(NQx,  512,  256, in_query, W_query, p_init, DIx);
    precompute_kernel<<<NTOK, QPx>>>(dist, W_bc, W_dt, dt_bias, A_log);
    scan_kernel<<<128, 320>>>();
    gate_rms_kernel<<<NTOK, 256>>>(Dv, key_nw);
    lnorm_kernel<<<NQx, 256>>>(q_nw, q_nb);
    sgemm_nt<<<dim3(4,32), 256>>>(NTOK, 256, 512, p_kf, W_out_key, out, 256);
    sgemm_nt<<<dim3(4,5),  256>>>(NQx,  256, 512, p_ln, W_out_qry, out + (size_t)NTOK*256, 256);
}

// round 17
// speedup vs baseline: 1.2368x; 1.0035x over previous
#include <cuda_runtime.h>
#include <math.h>

#define BBx 2
#define LLx 2048
#define HHx 8
#define PPx 64
#define DIx 512
#define NDx 16
#define QQx 300
#define QPx 320
#define LDZ 1040
#define NTOK 4096
#define NQx 600

typedef unsigned long long u64;

__device__ __align__(16) float g_zx  [NTOK*LDZ];
__device__ __align__(16) float g_init[NQx*DIx];
__device__ __align__(16) float g_dA  [NTOK*HHx*QPx];
__device__ __align__(16) float g_dtB [NTOK*HHx*QPx];
__device__ __align__(16) float g_C   [NTOK*QPx];
__device__ __align__(16) float g_y   [NTOK*DIx];
__device__ __align__(16) float g_S   [NQx*DIx];
__device__ __align__(16) float g_kf  [NTOK*DIx];
__device__ __align__(16) float g_ln  [NQx*DIx];

__device__ __forceinline__ void ld4(const float* p, float* v) {
    float4 t = *(const float4*)p;
    v[0]=t.x; v[1]=t.y; v[2]=t.z; v[3]=t.w;
}
__device__ __forceinline__ u64 f2mul(u64 a, u64 b){
    u64 r; asm("mul.rn.f32x2 %0,%1,%2;":"=l"(r):"l"(a),"l"(b)); return r;
}
__device__ __forceinline__ u64 f2fma(u64 a, u64 b, u64 c){
    u64 r; asm("fma.rn.f32x2 %0,%1,%2,%3;":"=l"(r):"l"(a),"l"(b),"l"(c)); return r;
}
__device__ __forceinline__ u64 fdup(float x){
    u64 r; asm("mov.b64 %0,{%1,%1};":"=l"(r):"f"(x)); return r;
}
__device__ __forceinline__ u64 fpack(float lo, float hi){
    u64 r; asm("mov.b64 %0,{%1,%2};":"=l"(r):"f"(lo),"f"(hi)); return r;
}
__device__ __forceinline__ void funpk(u64 v, float& lo, float& hi){
    asm("mov.b64 {%0,%1},%2;":"=f"(lo),"=f"(hi):"l"(v));
}

// ---------- SGEMM: C[M,N] = A[M,K] @ B[N,K]^T ; K % 16 == 0 ----------
// R12 structure, A-fragment reads vectorized to 2x LDS.128 (LDS/kk: 9 -> 3).
__global__ __launch_bounds__(256) void sgemm_nt(
    int M, int N, int K,
    const float* __restrict__ A, const float* __restrict__ B,
    float* __restrict__ C, int ldc)
{
    __shared__ float As[16][132];
    __shared__ float Bs[16][68];
    const int tid = threadIdx.x;
    const int tx = tid & 15, ty = tid >> 4;
    const int m0 = blockIdx.y*128, n0 = blockIdx.x*64;
    float acc[8][4];
#pragma unroll
    for (int i=0;i<8;i++)
#pragma unroll
        for (int j=0;j<4;j++) acc[i][j]=0.f;

    for (int k0=0;k0<K;k0+=16) {
#pragma unroll
        for (int i=0;i<2;i++) {
            int idx = tid + i*256;
            int ar = idx >> 2, ac = (idx & 3) << 2;
            int gm = m0 + ar;
            float4 v = make_float4(0.f,0.f,0.f,0.f);
            if (gm < M) v = *(const float4*)(A + (size_t)gm*K + k0 + ac);
            As[ac+0][ar]=v.x; As[ac+1][ar]=v.y; As[ac+2][ar]=v.z; As[ac+3][ar]=v.w;
        }
        {
            int br = tid >> 2, bc = (tid & 3) << 2;
            int gn = n0 + br;
            float4 v = make_float4(0.f,0.f,0.f,0.f);
            if (gn < N) v = *(const float4*)(B + (size_t)gn*K + k0 + bc);
            Bs[bc+0][br]=v.x; Bs[bc+1][br]=v.y; Bs[bc+2][br]=v.z; Bs[bc+3][br]=v.w;
        }
        __syncthreads();
#pragma unroll
        for (int kk=0;kk<16;kk++) {
            float a[8], bb[4];
            *(float4*)(a)   = *(const float4*)&As[kk][ty*8];
            *(float4*)(a+4) = *(const float4*)&As[kk][ty*8+4];
            float4 bv = *(const float4*)&Bs[kk][tx*4];
            bb[0]=bv.x; bb[1]=bv.y; bb[2]=bv.z; bb[3]=bv.w;
#pragma unroll
            for (int i=0;i<8;i++)
#pragma unroll
                for (int j=0;j<4;j++) acc[i][j] = fmaf(a[i], bb[j], acc[i][j]);
        }
        __syncthreads();
    }
#pragma unroll
    for (int i=0;i<8;i++) {
        int gm = m0 + ty*8 + i;
        if (gm < M)
#pragma unroll
            for (int j=0;j<4;j++) {
                int gn = n0 + tx*4 + j;
                if (gn < N) C[(size_t)gm*ldc + gn] = acc[i][j];
            }
    }
}

// per-token: B,C,dt -> g_dA, g_dtB, g_C (0.5 folded); zeroes g_y/g_S rows.
__global__ __launch_bounds__(QPx) void precompute_kernel(
    const float* __restrict__ dist, const float* __restrict__ W_bc,
    const float* __restrict__ W_dt, const float* __restrict__ dt_bias,
    const float* __restrict__ A_log)
{
    const int bt = blockIdx.x;
    const int n  = threadIdx.x;

    for (int i = n; i < DIx; i += QPx) {
        g_y[(size_t)bt*DIx + i] = 0.f;
        if (bt < NQx) g_S[(size_t)bt*DIx + i] = 0.f;
    }

    __shared__ float swbc[32], swdt[128], sdtb[8], sA[8], stok[10];
    if (n < 32) swbc[n] = W_bc[n];
    if (n >= 32 && n < 160) swdt[n-32] = W_dt[n-32];
    if (n >= 160 && n < 168) {
        sdtb[n-160] = dt_bias[n-160];
        sA[n-160]   = -expf(A_log[n-160]);
    }
    if (n >= 168 && n < 178) stok[n-168] = g_zx[(size_t)bt*LDZ + 1024 + (n-168)];
    __syncthreads();

    const bool valid = (n < QQx);
    float d[16];
    if (valid) {
        const float* dp = dist + ((size_t)bt*QQx + n)*NDx;
        ld4(dp,d); ld4(dp+4,d+4); ld4(dp+8,d+8); ld4(dp+12,d+12);
    } else {
#pragma unroll
        for (int i=0;i<16;i++) d[i]=0.f;
    }
    float bc0=0.f, bc1=0.f;
#pragma unroll
    for (int i=0;i<16;i++) {
        bc0 = fmaf(d[i], swbc[i],    bc0);
        bc1 = fmaf(d[i], swbc[16+i], bc1);
    }
    float Bv = bc0 + stok[0];
    float Cv = bc1 + stok[1];
    g_C[(size_t)bt*QPx + n] = valid ? 0.5f*Cv : 0.f;
#pragma unroll
    for (int h=0;h<8;h++) {
        float db = 0.f;
#pragma unroll
        for (int i=0;i<16;i++) db = fmaf(d[i], swdt[h*16+i], db);
        float v  = db + stok[2+h] + sdtb[h];
        float dt = (v > 20.f) ? v : log1pf(expf(v));
        size_t o = ((size_t)bt*HHx + h)*QPx + n;
        g_dA[o]  = valid ? expf(dt*sA[h]) : 0.f;
        g_dtB[o] = valid ? dt*Bv : 0.f;
    }
}

// scan v9 (R15-proven): 128 blocks (pg4,h8,b2,dir2); 320 threads (10 warps);
// 4p x 4n tiles; 4-deep pipeline; f32x2; 8-step recursive-halving reduction.
template<int STP>
__device__ __forceinline__ void scan_body(int pg, int h, int b) {
    const int tid = threadIdx.x, w = tid >> 5, lane = tid & 31;
    const int p_pair = lane >> 3, n_sub = lane & 7;
    const int n0 = w*32 + n_sub*4;
    const int p0 = pg*16 + p_pair*4;

    constexpr long SA = (long)STP*(HHx*QPx);
    constexpr long SC = (long)STP*QPx;
    constexpr long SX = (long)STP*LDZ;
    constexpr long SY = (long)STP*DIx;

    u64 S[4][2];
    {
        float si[4][4];
#pragma unroll
        for (int jn=0;jn<4;jn++) {
            int n = n0 + jn;
            if (n < QQx) ld4(&g_init[((size_t)(b*QQx+n))*DIx + h*PPx + p0], si[jn]);
            else { si[jn][0]=0.f; si[jn][1]=0.f; si[jn][2]=0.f; si[jn][3]=0.f; }
        }
#pragma unroll
        for (int pi=0;pi<4;pi++)
#pragma unroll
            for (int jp=0;jp<2;jp++)
                S[pi][jp] = fpack(si[2*jp][pi], si[2*jp+1][pi]);
    }

    const int bL = b*LLx;
    const int t0 = (STP < 0) ? (LLx-1) : 0;

    const float* pA = g_dA  + ((size_t)(bL+t0)*HHx + h)*QPx + n0;
    const float* pU = g_dtB + ((size_t)(bL+t0)*HHx + h)*QPx + n0;
    const float* pC = g_C   + (size_t)(bL+t0)*QPx + n0;
    const float* pX = g_zx  + (size_t)(bL+t0)*LDZ + DIx + h*PPx + p0;
    float*       pYl = g_y  + (size_t)(bL+t0)*DIx + h*PPx + p0 + (long)n_sub*SY;

    u64 av[4][2], uv[4][2], cv[4][2];
    float xv[4][4];
#pragma unroll
    for (int i=0;i<4;i++) {
        ulonglong2 ta = *(const ulonglong2*)(pA + i*SA); av[i][0]=ta.x; av[i][1]=ta.y;
        ulonglong2 tu = *(const ulonglong2*)(pU + i*SA); uv[i][0]=tu.x; uv[i][1]=tu.y;
        ulonglong2 tc = *(const ulonglong2*)(pC + i*SC); cv[i][0]=tc.x; cv[i][1]=tc.y;
        ld4(pX + i*SX, xv[i]);
    }
    pA += 4*SA; pU += 4*SA; pC += 4*SC; pX += 4*SX;

    float yb[4][8];

    for (int s0 = 0; s0 < LLx; s0 += 8) {
        const bool g1ld = (s0 + 8 < LLx);
#pragma unroll
        for (int g = 0; g < 2; g++) {
#pragma unroll
            for (int i=0;i<4;i++) {
#pragma unroll
                for (int pi=0;pi<4;pi++) {
                    u64 xd = fdup(xv[i][pi]);
                    u64 y  = 0ULL;
#pragma unroll
                    for (int jp=0;jp<2;jp++) {
                        S[pi][jp] = f2fma(S[pi][jp], av[i][jp], f2mul(uv[i][jp], xd));
                        y = f2fma(S[pi][jp], cv[i][jp], y);
                    }
                    float ya, ybv;
                    funpk(y, ya, ybv);
                    yb[pi][g*4+i] = ya + ybv;
                }
                if (g == 0 || g1ld) {
                    const long o = (g*4 + i);
                    ulonglong2 ta = *(const ulonglong2*)(pA + o*SA); av[i][0]=ta.x; av[i][1]=ta.y;
                    ulonglong2 tu = *(const ulonglong2*)(pU + o*SA); uv[i][0]=tu.x; uv[i][1]=tu.y;
                    ulonglong2 tc = *(const ulonglong2*)(pC + o*SC); cv[i][0]=tc.x; cv[i][1]=tc.y;
                    ld4(pX + o*SX, xv[i]);
                }
            }
        }
        pA += 8*SA; pU += 8*SA; pC += 8*SC; pX += 8*SX;

#pragma unroll
        for (int pi=0;pi<4;pi++) {
#pragma unroll
            for (int j = 0, m = 1; j < 3; j++, m <<= 1) {
                const int len = 8 >> (j + 1);
                const bool hi = (n_sub & m) != 0;
#pragma unroll
                for (int k = 0; k < len; k++) {
                    float send = hi ? yb[pi][2*k]   : yb[pi][2*k+1];
                    float keep = hi ? yb[pi][2*k+1] : yb[pi][2*k];
                    float r = __shfl_xor_sync(0xffffffffu, send, m);
                    yb[pi][k] = keep + r;
                }
            }
        }
        atomicAdd(pYl+0, yb[0][0]);
        atomicAdd(pYl+1, yb[1][0]);
        atomicAdd(pYl+2, yb[2][0]);
        atomicAdd(pYl+3, yb[3][0]);
        pYl += 8*SY;
    }

#pragma unroll
    for (int jp=0;jp<2;jp++) {
        float sa[4], sb[4];
#pragma unroll
        for (int pi=0;pi<4;pi++) funpk(S[pi][jp], sa[pi], sb[pi]);
        int na = n0 + 2*jp, nb = na + 1;
        if (na < QQx) {
            float* sp = &g_S[((size_t)(b*QQx+na))*DIx + h*PPx + p0];
#pragma unroll
            for (int pi=0;pi<4;pi++) atomicAdd(sp+pi, 0.5f*sa[pi]);
        }
        if (nb < QQx) {
            float* sp = &g_S[((size_t)(b*QQx+nb))*DIx + h*PPx + p0];
#pragma unroll
            for (int pi=0;pi<4;pi++) atomicAdd(sp+pi, 0.5f*sb[pi]);
        }
    }
}

__global__ __launch_bounds__(320, 1) void scan_kernel() {
    const int bx  = blockIdx.x;
    const int pg  = bx & 3;
    const int h   = (bx >> 2) & 7;
    const int b   = (bx >> 5) & 1;
    const int dir = (bx >> 6) & 1;
    if (dir == 0) scan_body<1>(pg, h, b);
    else          scan_body<-1>(pg, h, b);
}

__global__ __launch_bounds__(256) void gate_rms_kernel(
    const float* __restrict__ Dv, const float* __restrict__ knw)
{
    const int row = blockIdx.x, tid = threadIdx.x;
    float g[2]; float ss = 0.f;
#pragma unroll
    for (int e2=0;e2<2;e2++) {
        int e = tid + e2*256;
        float y = g_y [(size_t)row*DIx + e];
        float x = g_zx[(size_t)row*LDZ + DIx + e];
        float z = g_zx[(size_t)row*LDZ + e];
        float gg = (y + x*Dv[e>>6]) * (z / (1.f + expf(-z)));
        g[e2] = gg;
        ss += gg*gg;
    }
#pragma unroll
    for (int o=16;o;o>>=1) ss += __shfl_xor_sync(0xffffffffu, ss, o);
    __shared__ float red[8];
    if ((tid & 31) == 0) red[tid>>5] = ss;
    __syncthreads();
    if (tid == 0) {
        float tot = 0.f;
#pragma unroll
        for (int i=0;i<8;i++) tot += red[i];
        red[0] = rsqrtf(tot/512.f + 1e-5f);
    }
    __syncthreads();
    float sc = red[0];
#pragma unroll
    for (int e2=0;e2<2;e2++) {
        int e = tid + e2*256;
        g_kf[(size_t)row*DIx + e] = g[e2]*sc*knw[e];
    }
}

__global__ __launch_bounds__(256) void lnorm_kernel(
    const float* __restrict__ wn, const float* __restrict__ bn)
{
    const int row = blockIdx.x, tid = threadIdx.x;
    float v[2]; float s1 = 0.f, s2 = 0.f;
#pragma unroll
    for (int e2=0;e2<2;e2++) {
        int e = tid + e2*256;
        float x = g_S[(size_t)row*DIx + e];
        v[e2] = x; s1 += x; s2 += x*x;
    }
#pragma unroll
    for (int o=16;o;o>>=1) {
        s1 += __shfl_xor_sync(0xffffffffu, s1, o);
        s2 += __shfl_xor_sync(0xffffffffu, s2, o);
    }
    __shared__ float r1[8], r2[8];
    if ((tid & 31) == 0) { r1[tid>>5] = s1; r2[tid>>5] = s2; }
    __syncthreads();
    __shared__ float smu, sisd;
    if (tid == 0) {
        float a=0.f, bq=0.f;
#pragma unroll
        for (int i=0;i<8;i++) { a += r1[i]; bq += r2[i]; }
        float mu = a/512.f;
        smu = mu;
        sisd = rsqrtf(bq/512.f - mu*mu + 1e-5f);
    }
    __syncthreads();
    float mu = smu, isd = sisd;
#pragma unroll
    for (int e2=0;e2<2;e2++) {
        int e = tid + e2*256;
        g_ln[(size_t)row*DIx + e] = (v[e2]-mu)*isd*wn[e] + bn[e];
    }
}

extern "C" void kernel_launch(void* const* d_in, const int* in_sizes, int n_in,
                              void* d_out, int out_size) {
    const float* in_key    = (const float*)d_in[0];
    const float* in_query  = (const float*)d_in[1];
    const float* dist      = (const float*)d_in[2];
    const float* W_key     = (const float*)d_in[3];
    const float* W_query   = (const float*)d_in[4];
    const float* W_bc      = (const float*)d_in[5];
    const float* W_dt      = (const float*)d_in[6];
    const float* dt_bias   = (const float*)d_in[7];
    const float* A_log     = (const float*)d_in[8];
    const float* Dv        = (const float*)d_in[9];
    const float* W_out_key = (const float*)d_in[10];
    const float* W_out_qry = (const float*)d_in[11];
    const float* key_nw    = (const float*)d_in[12];
    const float* q_nw      = (const float*)d_in[13];
    const float* q_nb      = (const float*)d_in[14];
    float* out = (float*)d_out;

    float *p_zx, *p_init, *p_kf, *p_ln;
    cudaGetSymbolAddress((void**)&p_zx,   g_zx);
    cudaGetSymbolAddress((void**)&p_init, g_init);
    cudaGetSymbolAddress((void**)&p_kf,   g_kf);
    cudaGetSymbolAddress((void**)&p_ln,   g_ln);

    sgemm_nt<<<dim3(17,32), 256>>>(NTOK, 1034, 256, in_key,   W_key,   p_zx,   LDZ);
    sgemm_nt<<<dim3(8,5),   256>>>(NQx,  512,  256, in_query, W_query, p_init, DIx);
    precompute_kernel<<<NTOK, QPx>>>(dist, W_bc, W_dt, dt_bias, A_log);
    scan_kernel<<<128, 320>>>();
    gate_rms_kernel<<<NTOK, 256>>>(Dv, key_nw);
    lnorm_kernel<<<NQx, 256>>>(q_nw, q_nb);
    sgemm_nt<<<dim3(4,32), 256>>>(NTOK, 256, 512, p_kf, W_out_key, out, 256);
    sgemm_nt<<<dim3(4,5),  256>>>(NQx,  256, 512, p_ln, W_out_qry, out + (size_t)NTOK*256, 256);
}